// round 2
// baseline (speedup 1.0000x reference)
#include <cuda_runtime.h>

#define T_LEN 2048
#define E_N   19
#define B_N   64
#define H_N   32

typedef unsigned long long u64;

// final hidden states: [b][e][dir][l] -> ((b*E + e)*2 + d)*H + l
__device__ float g_hfinal[B_N * E_N * 2 * H_N];

__device__ __forceinline__ u64 ffma2(u64 a, u64 b, u64 c) {
    u64 d;
    asm("fma.rn.f32x2 %0, %1, %2, %3;" : "=l"(d) : "l"(a), "l"(b), "l"(c));
    return d;
}
__device__ __forceinline__ u64 pack2(float lo, float hi) {
    u64 r;
    asm("mov.b64 %0, {%1, %2};" : "=l"(r) : "f"(lo), "f"(hi));
    return r;
}
__device__ __forceinline__ void unpack2(u64 v, float &lo, float &hi) {
    asm("mov.b64 {%0, %1}, %2;" : "=f"(lo), "=f"(hi) : "l"(v));
}
// 1/(1+2^a) : gate pre-activations arrive pre-scaled by -log2(e) (folded into W)
__device__ __forceinline__ float gate_sig(float a) {
    float e, r;
    asm("ex2.approx.f32 %0, %1;" : "=f"(e) : "f"(a));
    asm("rcp.approx.f32 %0, %1;" : "=f"(r) : "f"(1.0f + e));
    return r;
}
// tanh from pre-scaled arg (a = -2*log2(e)*x folded into W): 2/(1+2^a) - 1
__device__ __forceinline__ float gate_tanh(float a) {
    return fmaf(2.0f, gate_sig(a), -1.0f);
}
// tanh with runtime arg (for cell state)
__device__ __forceinline__ float fast_tanh(float x) {
    return gate_tanh(x * -2.8853900817779268f);
}

#define C_SIG  (-1.4426950408889634f)
#define C_TANH (-2.8853900817779268f)

// One warp handles NI batch items of the same (electrode, direction).
// Lane l owns hidden index l (gate rows i=l, f=32+l, g=64+l, o=96+l).
// W_hh register-resident, gate-pair packed f32x2 with activation scales folded in.
// h exchanged via dup-packed smem double buffer, broadcast LDS.128, warp-local sync.
template <int NI>
__device__ __forceinline__ void run_lstm(
    const float* __restrict__ x, const float* __restrict__ w_ih,
    const float* __restrict__ w_hh, const float* __restrict__ b_ih,
    const float* __restrict__ b_hh,
    int ed, int b0, int lane, u64* hb /* [2][NI][32] region, stride 2*3*32 alloc */)
{
    const int e = ed >> 1;
    const int d = ed & 1;

    // ---- recurrent weights -> registers, (i,f)/(g,o) packed, scales folded ----
    const float* Wrow = w_hh + (ed * 4 * H_N + lane) * H_N;
    u64 Wif[H_N], Wgo[H_N];
#pragma unroll
    for (int j = 0; j < H_N / 4; j++) {
        float4 wi = *(const float4*)(Wrow + 0 * H_N * H_N + 4 * j);
        float4 wf = *(const float4*)(Wrow + 1 * H_N * H_N + 4 * j);
        float4 wg = *(const float4*)(Wrow + 2 * H_N * H_N + 4 * j);
        float4 wo = *(const float4*)(Wrow + 3 * H_N * H_N + 4 * j);
        Wif[4*j+0] = pack2(C_SIG * wi.x, C_SIG * wf.x);
        Wif[4*j+1] = pack2(C_SIG * wi.y, C_SIG * wf.y);
        Wif[4*j+2] = pack2(C_SIG * wi.z, C_SIG * wf.z);
        Wif[4*j+3] = pack2(C_SIG * wi.w, C_SIG * wf.w);
        Wgo[4*j+0] = pack2(C_TANH * wg.x, C_SIG * wo.x);
        Wgo[4*j+1] = pack2(C_TANH * wg.y, C_SIG * wo.y);
        Wgo[4*j+2] = pack2(C_TANH * wg.z, C_SIG * wo.z);
        Wgo[4*j+3] = pack2(C_TANH * wg.w, C_SIG * wo.w);
    }
    const int gb = ed * 4 * H_N + lane;
    const u64 bias_if = pack2(C_SIG  * (b_ih[gb]           + b_hh[gb]),
                              C_SIG  * (b_ih[gb +     H_N] + b_hh[gb +     H_N]));
    const u64 bias_go = pack2(C_TANH * (b_ih[gb + 2 * H_N] + b_hh[gb + 2 * H_N]),
                              C_SIG  * (b_ih[gb + 3 * H_N] + b_hh[gb + 3 * H_N]));
    const u64 wih_if  = pack2(C_SIG  * w_ih[gb],           C_SIG * w_ih[gb + H_N]);
    const u64 wih_go  = pack2(C_TANH * w_ih[gb + 2 * H_N], C_SIG * w_ih[gb + 3 * H_N]);

    // ---- state init ----
    float c[NI], hv[NI], xc[NI];
    const float* xp[NI];
    const int tstart = d ? (T_LEN - 1) : 0;
    const int stride = d ? -E_N : E_N;
#pragma unroll
    for (int i = 0; i < NI; i++) {
        c[i] = 0.f; hv[i] = 0.f;
        hb[0 * 3 * H_N + i * H_N + lane] = 0ull;
        xp[i] = x + ((long long)(b0 + i) * T_LEN + tstart) * E_N + e;
        xc[i] = __ldg(xp[i]);
    }
    __syncwarp();

    int cur = 0;
#pragma unroll 1
    for (int t = 0; t < T_LEN; t++) {
        float xn[NI];
        if (t < T_LEN - 1) {
#pragma unroll
            for (int i = 0; i < NI; i++) { xp[i] += stride; }
        }
#pragma unroll
        for (int i = 0; i < NI; i++) xn[i] = __ldg(xp[i]);

        u64 aif[NI], ago[NI];
#pragma unroll
        for (int i = 0; i < NI; i++) {
            u64 xd = pack2(xc[i], xc[i]);
            aif[i] = ffma2(xd, wih_if, bias_if);
            ago[i] = ffma2(xd, wih_go, bias_go);
        }

        const ulonglong2* hbc = (const ulonglong2*)(hb + cur * 3 * H_N);
#pragma unroll
        for (int j = 0; j < H_N / 2; j++) {
#pragma unroll
            for (int i = 0; i < NI; i++) {
                ulonglong2 hh = hbc[i * (H_N / 2) + j];  // 2 dup-packed h values
                aif[i] = ffma2(Wif[2*j],   hh.x, aif[i]);
                ago[i] = ffma2(Wgo[2*j],   hh.x, ago[i]);
                aif[i] = ffma2(Wif[2*j+1], hh.y, aif[i]);
                ago[i] = ffma2(Wgo[2*j+1], hh.y, ago[i]);
            }
        }

        const int nxt = cur ^ 1;
#pragma unroll
        for (int i = 0; i < NI; i++) {
            float ai, af, ag, ao;
            unpack2(aif[i], ai, af);
            unpack2(ago[i], ag, ao);
            float si = gate_sig(ai);
            float sf = gate_sig(af);
            float tg = gate_tanh(ag);
            float so = gate_sig(ao);
            c[i]  = fmaf(sf, c[i], si * tg);
            hv[i] = so * fast_tanh(c[i]);
            hb[nxt * 3 * H_N + i * H_N + lane] = pack2(hv[i], hv[i]);
        }
        __syncwarp();
        cur = nxt;
#pragma unroll
        for (int i = 0; i < NI; i++) xc[i] = xn[i];
    }

#pragma unroll
    for (int i = 0; i < NI; i++)
        g_hfinal[((b0 + i) * E_N + e) * 2 * H_N + d * H_N + lane] = hv[i];
}

// 296 CTAs x 128 threads -> exactly 2 CTAs/SM, 2 warps/SMSP.
// 1184 warps carry 2432 items: eds 0..31 -> 31 warps (k<29: 2 items, k=29/30: 3),
// eds 32..37 -> 32 warps (2 items each). Max 5 items per SMSP (optimal).
__global__ void __launch_bounds__(128, 2)
lstm_kernel(const float* __restrict__ x,
            const float* __restrict__ w_ih,
            const float* __restrict__ w_hh,
            const float* __restrict__ b_ih,
            const float* __restrict__ b_hh)
{
    __shared__ u64 hbuf[4][2][3][H_N];
    const int wid  = threadIdx.x >> 5;
    const int lane = threadIdx.x & 31;
    const int W    = blockIdx.x * 4 + wid;

    int ed, k;
    if (W < 992) { ed = W / 31; k = W - ed * 31; }
    else         { int r = W - 992; ed = 32 + (r >> 5); k = r & 31; }

    u64* hb = &hbuf[wid][0][0][0];
    if (W < 992 && k >= 29) {
        run_lstm<3>(x, w_ih, w_hh, b_ih, b_hh, ed, 58 + (k - 29) * 3, lane, hb);
    } else {
        run_lstm<2>(x, w_ih, w_hh, b_ih, b_hh, ed, 2 * k, lane, hb);
    }
}

// Per-batch epilogue: per-electrode LayerNorm over 64 features, electrode mean, FC.
__global__ void __launch_bounds__(64)
head_kernel(const float* __restrict__ ln_gamma,  // [E, 64]
            const float* __restrict__ ln_beta,   // [E, 64]
            const float* __restrict__ fc_w,      // [1, 64]
            const float* __restrict__ fc_b,      // [1]
            float* __restrict__ out)             // [B]
{
    const int b = blockIdx.x;
    const int f = threadIdx.x;
    __shared__ float red[4];
    const float* hbp = g_hfinal + b * (E_N * 2 * H_N);

    float pooled = 0.f;
    for (int e = 0; e < E_N; e++) {
        float v = hbp[e * 64 + f];
        float s = v, s2 = v * v;
#pragma unroll
        for (int off = 16; off; off >>= 1) {
            s  += __shfl_xor_sync(0xffffffffu, s,  off);
            s2 += __shfl_xor_sync(0xffffffffu, s2, off);
        }
        if ((f & 31) == 0) { red[(f >> 5) * 2] = s; red[(f >> 5) * 2 + 1] = s2; }
        __syncthreads();
        float S = red[0] + red[2], S2 = red[1] + red[3];
        __syncthreads();
        float mu  = S * (1.0f / 64.0f);
        float var = fmaf(-mu, mu, S2 * (1.0f / 64.0f));
        float nv  = (v - mu) * rsqrtf(var + 1e-5f);
        pooled += fmaf(nv, ln_gamma[e * 64 + f], ln_beta[e * 64 + f]);
    }
    pooled *= (1.0f / (float)E_N);

    float a = pooled * fc_w[f];
#pragma unroll
    for (int off = 16; off; off >>= 1) a += __shfl_xor_sync(0xffffffffu, a, off);
    if ((f & 31) == 0) red[f >> 5] = a;
    __syncthreads();
    if (f == 0) out[b] = red[0] + red[1] + fc_b[0];
}

extern "C" void kernel_launch(void* const* d_in, const int* in_sizes, int n_in,
                              void* d_out, int out_size) {
    const float* x        = (const float*)d_in[0];
    const float* w_ih     = (const float*)d_in[1];
    const float* w_hh     = (const float*)d_in[2];
    const float* b_ih     = (const float*)d_in[3];
    const float* b_hh     = (const float*)d_in[4];
    const float* ln_gamma = (const float*)d_in[5];
    const float* ln_beta  = (const float*)d_in[6];
    const float* fc_w     = (const float*)d_in[7];
    const float* fc_b     = (const float*)d_in[8];
    float* out = (float*)d_out;

    lstm_kernel<<<296, 128>>>(x, w_ih, w_hh, b_ih, b_hh);
    head_kernel<<<B_N, 64>>>(ln_gamma, ln_beta, fc_w, fc_b, out);
}